// round 16
// baseline (speedup 1.0000x reference)
#include <cuda_runtime.h>
#include <cstddef>

#define TT 1024
#define BB 8
#define VV 32000
#define EE 32
#define HH 8
#define NROWS (TT*BB)      // 8192
#define VBLK  25           // grid.x of the fused pass kernel
#define VITER 10           // outer iters; per iter a warp covers 8 tile-pairs = 128 v
#define LOG2E 1.4426950408889634f
#define LN2   0.6931471805599453f

// ---------------- scratch (device globals; no allocation) ----------------
__device__ float  g_xp[2*TT*BB*HH];      // [dir][t][b][h]  -log2e * (input proj + biases)
__device__ float  g_totalH[TT*2*BB*HH];  // [t][dir][b][j]  coalesced for the rnn store
__device__ float  g_partial[VBLK*NROWS]; // per v-block partial sum-of-exp (deterministic)
__device__ float  g_rowstat[NROWS];      // log(sum exp) per row (natural log)
__device__ float  g_Wt1[16*VV];          // tiled tf32 W * log2e, 2 MB (single copy)
__device__ int    g_cnt[64];             // per slice: phase-A completion counters
__device__ int    g_flag[64];            // per slice: rowstat-ready flags
__device__ int    g_sliceCnt[64];        // per slice: rnn chain completion (16 = ready)
__device__ int    g_wflag[32];           // per bx: W region prepped
// pair-permuted tile layout: v-pair P = v>>4, u = v&15.
//   tile = 2P + ((u>>1)&1),  n = ((u>>2)<<1) | (u&1)
//   pos  = tile*128 + n*16 + (k&3)*4 + (k>>2)
// thread (g=n-group, q) then owns 4 CONSECUTIVE v = P*16 + 4q + {0,1,2,3}
// from the two tiles of a pair -> phase B emits STG.128.

// tf32 round (rna)
__device__ __forceinline__ unsigned tf32_of(float x) {
    unsigned r;
    asm("cvt.rna.tf32.f32 %0, %1;" : "=r"(r) : "f"(x));
    return r;
}
__device__ __forceinline__ float ex2(float x) {
    float r; asm("ex2.approx.f32 %0, %1;" : "=f"(r) : "f"(x)); return r;
}
__device__ __forceinline__ float rcp(float x) {
    float r; asm("rcp.approx.f32 %0, %1;" : "=f"(r) : "f"(x)); return r;
}

// m16n8k8 tf32 mma, D += A*B (C aliased to D)
__device__ __forceinline__ void mma_tf32(float& d0, float& d1, float& d2, float& d3,
                                         unsigned a0, unsigned a1, unsigned a2, unsigned a3,
                                         unsigned b0, unsigned b1) {
    asm("mma.sync.aligned.m16n8k8.row.col.f32.tf32.tf32.f32 "
        "{%0,%1,%2,%3}, {%4,%5,%6,%7}, {%8,%9}, {%0,%1,%2,%3};"
        : "+f"(d0), "+f"(d1), "+f"(d2), "+f"(d3)
        : "r"(a0), "r"(a1), "r"(a2), "r"(a3), "r"(b0), "r"(b1));
}

// blockIdx.y -> t-slice permutation. Slice y ready at rnn step max(16y+15, 1023-16y):
// middle slices earliest. ylin=0 (contains the 16 rnn-carrier blocks) gets y=0
// (ready last); ylin>=1 get middle-out slices so the earliest-scheduled
// non-carrier blocks wait the least. Cohort readiness is monotone in ylin
// (ylin 1,2 earliest ... ylin 63 and 0 last) -> used for the A/B pipeline chain.
__device__ __forceinline__ int slice_of(int ylin) {
    if (ylin == 0) return 0;
    int j = ylin - 1;                       // 0..62
    return (j & 1) ? (32 - ((j + 1) >> 1)) : (32 + (j >> 1));  // 32,31,33,30,...,1,63
}

// ---------------- kernel 1: embedding gather + x-projections + sync reset -----
// stores xp' = -log2e * (e@Wx + bx + bh) so the rnn uses ex2 directly
__global__ void k_embed(const int* __restrict__ x, const float* __restrict__ emb,
                        const float* __restrict__ Wx1, const float* __restrict__ bx1,
                        const float* __restrict__ bh1,
                        const float* __restrict__ Wx2, const float* __restrict__ bx2,
                        const float* __restrict__ bh2) {
    int tid = blockIdx.x * blockDim.x + threadIdx.x;   // (t,b) flat
    if (blockIdx.x == 0 && threadIdx.x < 64) {         // reset sync state per replay
        g_cnt[threadIdx.x] = 0;
        g_flag[threadIdx.x] = 0;
        g_sliceCnt[threadIdx.x] = 0;
        if (threadIdx.x < 32) g_wflag[threadIdx.x] = 0;
    }
    if (tid >= NROWS) return;
    int idx = x[tid];
    const float4* em = (const float4*)(emb + (size_t)idx * EE);
    float e[EE];
    #pragma unroll
    for (int q = 0; q < 8; q++) {
        float4 v = __ldg(em + q);
        e[4*q] = v.x; e[4*q+1] = v.y; e[4*q+2] = v.z; e[4*q+3] = v.w;
    }
    #pragma unroll
    for (int j = 0; j < HH; j++) {
        float s1 = bx1[j] + bh1[j];
        float s2 = bx2[j] + bh2[j];
        #pragma unroll
        for (int k = 0; k < EE; k++) {
            s1 = fmaf(e[k], __ldg(Wx1 + k*HH + j), s1);
            s2 = fmaf(e[k], __ldg(Wx2 + k*HH + j), s2);
        }
        g_xp[tid*HH + j] = s1 * (-LOG2E);
        g_xp[TT*BB*HH + tid*HH + j] = s2 * (-LOG2E);
    }
}

// ---------------- rnn chain (runs inside carrier blocks of the fused kernel) ---
// Threads 0..7 of the block; chain id c in 0..15. h exchange via double-buffered
// SMEM. Signals g_sliceCnt[t>>4] after finishing each 16-t slice (release).
__device__ void run_chain(int c, int j, float* sh,
                          const float* __restrict__ Wh1,
                          const float* __restrict__ Wh2) {
    int dir = c >> 3, b = c & 7;
    const float* Wh = dir ? Wh2 : Wh1;
    float w[HH];
    #pragma unroll
    for (int k = 0; k < HH; k++) w[k] = __ldg(Wh + k*HH + j) * (-LOG2E);

    const float* xp = g_xp + dir * (TT*BB*HH);
    float h = 0.f;

    // depth-4 prefetch ring
    float pf[4];
    #pragma unroll
    for (int p = 0; p < 4; p++) {
        int t = dir ? (TT - 1 - p) : p;
        pf[p] = __ldg(xp + (t*BB + b) * HH + j);
    }

    #pragma unroll 4
    for (int s = 0; s < TT; s++) {
        int slot = s & 3;
        float xv = pf[slot];
        if (s + 4 < TT) {
            int t4 = dir ? (TT - 1 - (s + 4)) : (s + 4);
            pf[slot] = __ldg(xp + (t4*BB + b) * HH + j);
        }
        int t = dir ? (TT - 1 - s) : s;
        // emit pre-update hidden state: [t][dir][b][j]
        g_totalH[t*128 + dir*64 + b*8 + j] = h;
        // slice boundary: dir0 ascending completes at t%16==15, dir1 at t%16==0
        if ((t & 15) == (dir ? 0 : 15)) {
            __syncwarp(0xffu);
            __threadfence();                 // release totalH stores
            if (j == 0) atomicAdd(&g_sliceCnt[t >> 4], 1);
        }
        // exchange h via smem (double-buffered by step parity)
        float* buf = sh + (s & 1) * 8;
        buf[j] = h;
        __syncwarp(0xffu);
        float4 lo = *(const float4*)(buf);       // broadcast LDS.128
        float4 hi = *(const float4*)(buf + 4);
        float t0 = fmaf(lo.y, w[1], lo.x * w[0]);
        float t1 = fmaf(lo.w, w[3], lo.z * w[2]);
        float t2 = fmaf(hi.y, w[5], hi.x * w[4]);
        float t3 = fmaf(hi.w, w[7], hi.z * w[6]);
        float z  = xv + ((t0 + t1) + (t2 + t3));
        h = rcp(1.f + ex2(z));              // sigmoid
    }
}

// ---------------- fused kernel: prep + rnn + pipelined GEMM/stat/output --------
// Grid (VBLK, 64), block 256.
//  * blocks (bx, ylin==1): prep W region bx first, flag it.
//  * blocks (bx<16, ylin==0): warp 0 lanes 0..7 run one rnn chain each.
//  * all blocks: phase A (2^d sums -> partials -> last-block stat -> flag) for
//    their OWN slice yA, then phase B (recompute, store) for the PREVIOUS
//    cohort's slice yB -- whose stat finished earlier, so blocks fall straight
//    from A into B and the chip pipelines A-compute against B's DRAM stream.
__global__ __launch_bounds__(256) void k_fused(float* __restrict__ out,
                                               const float* __restrict__ Wo,
                                               const float* __restrict__ Wh1,
                                               const float* __restrict__ Wh2) {
    __shared__ __align__(16) float sh_h[16];   // rnn h exchange (carriers only)

    // ---------------- W prep section (ylin == 1) ----------------
    if (blockIdx.y == 1) {
        int vbase = blockIdx.x * 1280;         // this bx's v range (160 tiles)
        #pragma unroll 1
        for (int k = 0; k < 16; k++) {
            #pragma unroll
            for (int it = 0; it < 5; it++) {
                int v = vbase + it * 256 + threadIdx.x;
                float x = __ldg(Wo + (size_t)k * VV + v);
                int P = v >> 4, u = v & 15;
                int tile = 2*P + ((u >> 1) & 1);
                int n = ((u >> 2) << 1) | (u & 1);
                int pos = tile*128 + n*16 + (k & 3)*4 + (k >> 2);
                g_Wt1[pos] = __uint_as_float(tf32_of(x * LOG2E));
            }
        }
        __threadfence();                       // publish W region
        __syncthreads();
        if (threadIdx.x == 0) atomicExch(&g_wflag[blockIdx.x], 1);
    }

    // ---------------- rnn carrier section (ylin == 0, bx < 16) ----------------
    if (blockIdx.y == 0 && blockIdx.x < 16) {
        if (threadIdx.x < 8)
            run_chain(blockIdx.x, threadIdx.x, sh_h, Wh1, Wh2);
        __syncthreads();                   // park warps 1..7 while warp 0 chains
    }

    int lane = threadIdx.x & 31, w = threadIdx.x >> 5;
    int g = lane >> 2, q = lane & 3;
    int ylin = blockIdx.y;
    int yA = slice_of(ylin);
    // B-slice: previous cohort (earlier-ready). Wraps: ylin=1 -> slice 0
    // (stat by carriers at rnn end), ylin=0 -> slice_of(63) (stat by the last
    // cohort). Every block runs phase A before any B-spin -> no deadlock.
    int yB = (ylin >= 2) ? slice_of(ylin - 1) : (ylin == 1 ? 0 : slice_of(63));
    int rowBaseA = yA * 128 + w * 16;

    int vt0 = blockIdx.x * (VITER * 16);   // first v-tile index of this block
    const float4* Bbase = (const float4*)(g_Wt1 + (size_t)vt0 * 128 + g * 16 + q * 4);

    // ---------------- wait for W region + phase-A t-slice ----------------
    if (threadIdx.x == 0) {
        while (atomicAdd(&g_wflag[blockIdx.x], 0) == 0) __nanosleep(100);
        while (atomicAdd(&g_sliceCnt[yA], 0) < 16) __nanosleep(100);
    }
    __syncthreads();
    __threadfence();                       // acquire totalH + W

    // ---------------- phase A: sums for slice yA ----------------
    {
        // A fragments for yA. jj: row g+(jj&1)*8, col q+(jj>>1)*4
        unsigned ah[2][4];
        #pragma unroll
        for (int kt = 0; kt < 2; kt++) {
            #pragma unroll
            for (int jj = 0; jj < 4; jj++) {
                int r = g + (jj & 1) * 8;
                int k = kt * 8 + q + ((jj >> 1) ? 4 : 0);
                int grow = rowBaseA + r, t = grow >> 3, b = grow & 7;
                ah[kt][jj] = tf32_of(g_totalH[t*128 + (k >> 3)*64 + b*8 + (k & 7)]);
            }
        }

        float sum0 = 0.f, sum1 = 0.f;
        const float4* Bt = Bbase;
        for (int it = 0; it < VITER; it++) {
            #pragma unroll
            for (int pr = 0; pr < 8; pr++) {       // 8 tile-pairs = 128 v per iter
                float4 B0 = __ldg(Bt);             // tile 2P
                float4 B1 = __ldg(Bt + 32);        // tile 2P+1
                Bt += 64;
                unsigned b000 = __float_as_uint(B0.x), b001 = __float_as_uint(B0.y);
                unsigned b010 = __float_as_uint(B0.z), b011 = __float_as_uint(B0.w);
                unsigned b100 = __float_as_uint(B1.x), b101 = __float_as_uint(B1.y);
                unsigned b110 = __float_as_uint(B1.z), b111 = __float_as_uint(B1.w);

                float e0 = 0.f, e1 = 0.f, e2 = 0.f, e3 = 0.f;
                mma_tf32(e0,e1,e2,e3, ah[0][0],ah[0][1],ah[0][2],ah[0][3], b000,b001);
                mma_tf32(e0,e1,e2,e3, ah[1][0],ah[1][1],ah[1][2],ah[1][3], b010,b011);
                float f0 = 0.f, f1 = 0.f, f2 = 0.f, f3 = 0.f;
                mma_tf32(f0,f1,f2,f3, ah[0][0],ah[0][1],ah[0][2],ah[0][3], b100,b101);
                mma_tf32(f0,f1,f2,f3, ah[1][0],ah[1][1],ah[1][2],ah[1][3], b110,b111);

                sum0 += (ex2(e0) + ex2(e1)) + (ex2(f0) + ex2(f1));
                sum1 += (ex2(e2) + ex2(e3)) + (ex2(f2) + ex2(f3));
            }
        }
        // reduce across the 4 q-lanes sharing each row-group g
        sum0 += __shfl_xor_sync(0xffffffffu, sum0, 1);
        sum0 += __shfl_xor_sync(0xffffffffu, sum0, 2);
        sum1 += __shfl_xor_sync(0xffffffffu, sum1, 1);
        sum1 += __shfl_xor_sync(0xffffffffu, sum1, 2);
        if (q == 0) {
            float* p = g_partial + (size_t)blockIdx.x * NROWS + rowBaseA;
            p[g    ] = sum0;
            p[g + 8] = sum1;
        }
    }

    // ---------------- stat by last-arriving block of slice yA ----------------
    __shared__ bool isLast;
    __threadfence();                       // publish partials (release)
    __syncthreads();
    if (threadIdx.x == 0) {
        int old = atomicAdd(&g_cnt[yA], 1);
        isLast = (old == VBLK - 1);
    }
    __syncthreads();
    if (isLast) {
        int r0 = yA * 128;
        for (int r = threadIdx.x; r < 128; r += 256) {
            float s = 0.f;
            #pragma unroll
            for (int i = 0; i < VBLK; i++)
                s += __ldcg(g_partial + (size_t)i * NROWS + r0 + r);
            g_rowstat[r0 + r] = logf(s);
        }
        __threadfence();                   // publish rowstat before flag
        __syncthreads();
        if (threadIdx.x == 0) atomicExch(&g_flag[yA], 1);
    }

    // ---------------- spin until slice yB's rowstat ready ----------------
    if (threadIdx.x == 0) {
        while (atomicAdd(&g_flag[yB], 0) == 0) __nanosleep(200);
    }
    __syncthreads();
    __threadfence();                       // acquire rowstat + totalH of yB

    int rowBaseB = yB * 128 + w * 16;
    float st0 = __ldcg(g_rowstat + rowBaseB + g);
    float st1 = __ldcg(g_rowstat + rowBaseB + g + 8);

    // ---------------- phase B: outputs for slice yB ----------------
    {
        // A fragments for yB (totalH[yB] complete: implied by flag[yB])
        unsigned ah[2][4];
        #pragma unroll
        for (int kt = 0; kt < 2; kt++) {
            #pragma unroll
            for (int jj = 0; jj < 4; jj++) {
                int r = g + (jj & 1) * 8;
                int k = kt * 8 + q + ((jj >> 1) ? 4 : 0);
                int grow = rowBaseB + r, t = grow >> 3, b = grow & 7;
                ah[kt][jj] = tf32_of(g_totalH[t*128 + (k >> 3)*64 + b*8 + (k & 7)]);
            }
        }

        const float4* Bt = Bbase;
        size_t vc = (size_t)vt0 * 8 + q * 4;   // P0*16 + 4q
        float* op0 = out + (size_t)(rowBaseB + g    ) * VV + vc;
        float* op1 = out + (size_t)(rowBaseB + g + 8) * VV + vc;

        for (int it = 0; it < VITER; it++) {
            #pragma unroll
            for (int pr = 0; pr < 8; pr++) {
                float4 B0 = __ldg(Bt);
                float4 B1 = __ldg(Bt + 32);
                Bt += 64;
                unsigned b000 = __float_as_uint(B0.x), b001 = __float_as_uint(B0.y);
                unsigned b010 = __float_as_uint(B0.z), b011 = __float_as_uint(B0.w);
                unsigned b100 = __float_as_uint(B1.x), b101 = __float_as_uint(B1.y);
                unsigned b110 = __float_as_uint(B1.z), b111 = __float_as_uint(B1.w);

                float e0 = 0.f, e1 = 0.f, e2 = 0.f, e3 = 0.f;
                mma_tf32(e0,e1,e2,e3, ah[0][0],ah[0][1],ah[0][2],ah[0][3], b000,b001);
                mma_tf32(e0,e1,e2,e3, ah[1][0],ah[1][1],ah[1][2],ah[1][3], b010,b011);
                float f0 = 0.f, f1 = 0.f, f2 = 0.f, f3 = 0.f;
                mma_tf32(f0,f1,f2,f3, ah[0][0],ah[0][1],ah[0][2],ah[0][3], b100,b101);
                mma_tf32(f0,f1,f2,f3, ah[1][0],ah[1][1],ah[1][2],ah[1][3], b110,b111);

                // natural logit = d * ln2 ; output = logit - logsumexp
                float4 o0 = make_float4(fmaf(e0, LN2, -st0), fmaf(e1, LN2, -st0),
                                        fmaf(f0, LN2, -st0), fmaf(f1, LN2, -st0));
                float4 o1 = make_float4(fmaf(e2, LN2, -st1), fmaf(e3, LN2, -st1),
                                        fmaf(f2, LN2, -st1), fmaf(f3, LN2, -st1));
                __stcs((float4*)op0, o0);
                __stcs((float4*)op1, o1);
                op0 += 16; op1 += 16;
            }
        }
    }
}

// ---------------- launch ----------------
extern "C" void kernel_launch(void* const* d_in, const int* in_sizes, int n_in,
                              void* d_out, int out_size) {
    const int*   x   = (const int*)  d_in[0];
    const float* emb = (const float*)d_in[1];
    const float* Wx1 = (const float*)d_in[2];
    const float* bx1 = (const float*)d_in[3];
    const float* Wh1 = (const float*)d_in[4];
    const float* bh1 = (const float*)d_in[5];
    const float* Wx2 = (const float*)d_in[6];
    const float* bx2 = (const float*)d_in[7];
    const float* Wh2 = (const float*)d_in[8];
    const float* bh2 = (const float*)d_in[9];
    const float* Wo  = (const float*)d_in[10];
    float* out = (float*)d_out;

    k_embed<<<(NROWS + 255)/256, 256>>>(x, emb, Wx1, bx1, bh1, Wx2, bx2, bh2);
    dim3 grd(VBLK, NROWS/128), blk(256);
    k_fused<<<grd, blk>>>(out, Wo, Wh1, Wh2);
}